// round 13
// baseline (speedup 1.0000x reference)
#include <cuda_runtime.h>
#include <cuda_bf16.h>

// LSTM_20452634263894: B=32768, T=512, I=2, H=16.
// Pair-split (proven numerics, R11) with halved h storage: each thread keeps
// ONLY its own 8 units' h per row; partner h obtained by fresh shfl.bfly(1)
// inside the matvec. No stored-partner copies, no exchange selects.
// Even lane owns units 0-7, odd lane units 8-15, both for rows (2p, 2p+1).
// Each weight LDS.128 feeds 4 ffma2. i/f/o rows pre-scaled by 0.5
// (sigmoid = 0.5*tanh(pre)+0.5). All local arrays constant-indexed.

#define B_TOT  32768
#define T_LEN  512
#define H_DIM  16
#define NTHR   128
#define NCTA   256   // 32768 threads: 1 thread per batch row, paired lanes

typedef unsigned long long u64;

__device__ __forceinline__ u64 pack2(float lo, float hi) {
    u64 r;
    asm("mov.b64 %0, {%1, %2};" : "=l"(r) : "f"(lo), "f"(hi));
    return r;
}
__device__ __forceinline__ void unpack2(u64 v, float& lo, float& hi) {
    asm("mov.b64 {%0, %1}, %2;" : "=f"(lo), "=f"(hi) : "l"(v));
}
__device__ __forceinline__ u64 ffma2(u64 a, u64 b, u64 c) {
    u64 d;
    asm("fma.rn.f32x2 %0, %1, %2, %3;" : "=l"(d) : "l"(a), "l"(b), "l"(c));
    return d;
}
__device__ __forceinline__ u64 mul2(u64 a, u64 b) {
    u64 d;
    asm("mul.rn.f32x2 %0, %1, %2;" : "=l"(d) : "l"(a), "l"(b));
    return d;
}
__device__ __forceinline__ float tanh_fast(float x) {
    float y;
    asm("tanh.approx.f32 %0, %1;" : "=f"(y) : "f"(x));
    return y;
}

// Smem u64 entry e (0..31) -> gate-pair p (verbatim from R11's pass).
__device__ __forceinline__ void decode_entry(int e, int& p, float& sc) {
    int j2 = e >> 2, par = (e >> 1) & 1, lane = e & 1;
    int s = 2 * j2 + lane;           // thread slot 0..15
    int grp = s >> 2, jj = s & 3;    // 0=i,1=f,2=g,3=o
    p = grp * 8 + par * 4 + jj;      // own unit pair = par*8 + 2jj (+1)
    sc = (grp == 2) ? 1.0f : 0.5f;
}

// Activation for one row's own 8 units (verbatim math from R11's pass,
// minus the exchange). a[0..3]=i, a[4..7]=f, a[8..11]=g, a[12..15]=o for
// own unit pair (2j, 2j+1); i/f/o pre-scaled by 0.5. Writes ho[2j],ho[2j+1].
__device__ __forceinline__ void act_row(u64 (&a)[16], u64 (&cc)[4],
                                        float (&ho)[8], u64 H05) {
#pragma unroll
    for (int j = 0; j < 4; ++j) {
        float u, v;
        unpack2(a[j], u, v);
        u64 i2 = ffma2(H05, pack2(tanh_fast(u), tanh_fast(v)), H05);
        unpack2(a[4 + j], u, v);
        u64 f2 = ffma2(H05, pack2(tanh_fast(u), tanh_fast(v)), H05);
        unpack2(a[8 + j], u, v);
        u64 g2 = pack2(tanh_fast(u), tanh_fast(v));
        unpack2(a[12 + j], u, v);
        u64 o2 = ffma2(H05, pack2(tanh_fast(u), tanh_fast(v)), H05);
        u64 cn = ffma2(f2, cc[j], mul2(i2, g2));
        cc[j] = cn;
        unpack2(cn, u, v);
        u64 hv = mul2(o2, pack2(tanh_fast(u), tanh_fast(v)));
        unpack2(hv, ho[2 * j], ho[2 * j + 1]);     // constant indices
    }
}

__global__ void __launch_bounds__(NTHR) lstm_split3_kernel(
    const float* __restrict__ x,
    const float* __restrict__ W_ih, const float* __restrict__ W_hh,
    const float* __restrict__ b_ih, const float* __restrict__ b_hh,
    const float* __restrict__ W1,  const float* __restrict__ b1,
    const float* __restrict__ W2,  const float* __restrict__ b2,
    float* __restrict__ out)
{
    __shared__ __align__(16) u64 sWhh[H_DIM][32];
    __shared__ __align__(16) u64 sWih[2][32];
    __shared__ __align__(16) u64 sBias[32];
    __shared__ float sW1[H_DIM * H_DIM];
    __shared__ float sb1[H_DIM];
    __shared__ float sW2[2 * H_DIM];
    __shared__ float sb2[2];

    const int tid = threadIdx.x;

    for (int idx = tid; idx < H_DIM * 32; idx += NTHR) {
        int k = idx >> 5, e = idx & 31;
        int p; float sc; decode_entry(e, p, sc);
        sWhh[k][e] = pack2(W_hh[(2 * p) * H_DIM + k] * sc,
                           W_hh[(2 * p + 1) * H_DIM + k] * sc);
    }
    for (int idx = tid; idx < 2 * 32; idx += NTHR) {
        int cc = idx >> 5, e = idx & 31;
        int p; float sc; decode_entry(e, p, sc);
        sWih[cc][e] = pack2(W_ih[(2 * p) * 2 + cc] * sc,
                            W_ih[(2 * p + 1) * 2 + cc] * sc);
    }
    for (int e = tid; e < 32; e += NTHR) {
        int p; float sc; decode_entry(e, p, sc);
        sBias[e] = pack2((b_ih[2 * p] + b_hh[2 * p]) * sc,
                         (b_ih[2 * p + 1] + b_hh[2 * p + 1]) * sc);
    }
    for (int idx = tid; idx < H_DIM * H_DIM; idx += NTHR) sW1[idx] = W1[idx];
    for (int idx = tid; idx < H_DIM; idx += NTHR) sb1[idx] = b1[idx];
    for (int idx = tid; idx < 2 * H_DIM; idx += NTHR) sW2[idx] = W2[idx];
    for (int idx = tid; idx < 2; idx += NTHR) sb2[idx] = b2[idx];
    __syncthreads();

    const int gt     = blockIdx.x * NTHR + tid;   // 32768 threads
    const int parity = gt & 1;
    const int rowA   = (gt >> 1) * 2;
    const int myu    = parity * 8;                // own units myu..myu+7
    const int otu    = 8 - myu;                   // partner units

    const float4* __restrict__ xpA =
        reinterpret_cast<const float4*>(x + (size_t)rowA * (T_LEN * 2));
    const float4* __restrict__ xpB =
        reinterpret_cast<const float4*>(x + (size_t)(rowA + 1) * (T_LEN * 2));

    float hAo[8], hBo[8];        // OWN units' hidden state only
    u64   cA[4], cB[4];          // own cell state, packed pairs
#pragma unroll
    for (int u = 0; u < 8; ++u) { hAo[u] = 0.0f; hBo[u] = 0.0f; }
#pragma unroll
    for (int j = 0; j < 4; ++j) { cA[j] = 0ull; cB[j] = 0ull; }

    const u64 H05 = pack2(0.5f, 0.5f);

    float4 xbA = __ldg(xpA);
    float4 xbB = __ldg(xpB);

#pragma unroll 1
    for (int t2 = 0; t2 < T_LEN / 2; ++t2) {
        const int tn = (t2 + 1 < T_LEN / 2) ? (t2 + 1) : t2;  // clamped
        float4 xnA = __ldg(xpA + tn);
        float4 xnB = __ldg(xpB + tn);

#pragma unroll
        for (int sub = 0; sub < 2; ++sub) {
            const float xA0 = sub ? xbA.z : xbA.x;
            const float xA1 = sub ? xbA.w : xbA.y;
            const float xB0 = sub ? xbB.z : xbB.x;
            const float xB1 = sub ? xbB.w : xbB.y;
            const u64 pA0 = pack2(xA0, xA0), pA1 = pack2(xA1, xA1);
            const u64 pB0 = pack2(xB0, xB0), pB1 = pack2(xB1, xB1);

            u64 aA[16], aB[16];

            const ulonglong2* __restrict__ bp =
                reinterpret_cast<const ulonglong2*>(&sBias[0]);
            const ulonglong2* __restrict__ wp0 =
                reinterpret_cast<const ulonglong2*>(&sWih[0][0]);
            const ulonglong2* __restrict__ wp1 =
                reinterpret_cast<const ulonglong2*>(&sWih[1][0]);
#pragma unroll
            for (int j = 0; j < 8; ++j) {
                const int e = 2 * j + parity;     // shared idx: dynamic OK
                ulonglong2 bb = bp[e];
                ulonglong2 w0 = wp0[e];
                ulonglong2 w1 = wp1[e];
                aA[2 * j]     = ffma2(pA1, w1.x, ffma2(pA0, w0.x, bb.x));
                aA[2 * j + 1] = ffma2(pA1, w1.y, ffma2(pA0, w0.y, bb.y));
                aB[2 * j]     = ffma2(pB1, w1.x, ffma2(pB0, w0.x, bb.x));
                aB[2 * j + 1] = ffma2(pB1, w1.y, ffma2(pB0, w0.y, bb.y));
            }

            // Matvec, own-k half: k = myu+u, h from own registers.
#pragma unroll
            for (int u = 0; u < 8; ++u) {
                const ulonglong2* __restrict__ wr =
                    reinterpret_cast<const ulonglong2*>(&sWhh[myu + u][0]);
                const u64 hkA = pack2(hAo[u], hAo[u]);
                const u64 hkB = pack2(hBo[u], hBo[u]);
#pragma unroll
                for (int j = 0; j < 8; ++j) {
                    ulonglong2 w = wr[2 * j + parity];
                    aA[2 * j]     = ffma2(hkA, w.x, aA[2 * j]);
                    aA[2 * j + 1] = ffma2(hkA, w.y, aA[2 * j + 1]);
                    aB[2 * j]     = ffma2(hkB, w.x, aB[2 * j]);
                    aB[2 * j + 1] = ffma2(hkB, w.y, aB[2 * j + 1]);
                }
            }
            // Matvec, partner-k half: k = otu+u, h via shfl of partner's own
            // (pre-update h; act runs after both halves). Uniform shfl.
#pragma unroll
            for (int u = 0; u < 8; ++u) {
                const float phA = __shfl_xor_sync(0xffffffffu, hAo[u], 1);
                const float phB = __shfl_xor_sync(0xffffffffu, hBo[u], 1);
                const ulonglong2* __restrict__ wr =
                    reinterpret_cast<const ulonglong2*>(&sWhh[otu + u][0]);
                const u64 hkA = pack2(phA, phA);
                const u64 hkB = pack2(phB, phB);
#pragma unroll
                for (int j = 0; j < 8; ++j) {
                    ulonglong2 w = wr[2 * j + parity];
                    aA[2 * j]     = ffma2(hkA, w.x, aA[2 * j]);
                    aA[2 * j + 1] = ffma2(hkA, w.y, aA[2 * j + 1]);
                    aB[2 * j]     = ffma2(hkB, w.x, aB[2 * j]);
                    aB[2 * j + 1] = ffma2(hkB, w.y, aB[2 * j + 1]);
                }
            }

            // Own-unit activations (statically-bound refs, proven math).
            act_row(aA, cA, hAo, H05);
            act_row(aB, cB, hBo, H05);
        } // sub
        xbA = xnA; xbB = xnB;
    }

    // MLP head. Gather the full h of the OUTPUT row (even->A, odd->B):
    //   even lane, row A: [u]=hAo[u] (units 0-7), [8+u]=shfl(hAo) (8-15)
    //   odd  lane, row B: [u]=shfl(hBo) (units 0-7), [8+u]=hBo[u] (8-15)
    float hfull[H_DIM];
#pragma unroll
    for (int u = 0; u < 8; ++u) {
        const float shA = __shfl_xor_sync(0xffffffffu, hAo[u], 1);
        const float shB = __shfl_xor_sync(0xffffffffu, hBo[u], 1);
        hfull[u]     = (parity == 0) ? hAo[u] : shB;
        hfull[8 + u] = (parity == 0) ? shA    : hBo[u];
    }

    float y0 = sb2[0], y1 = sb2[1];
#pragma unroll
    for (int j = 0; j < H_DIM; ++j) {
        float z = sb1[j];
#pragma unroll
        for (int k = 0; k < H_DIM; ++k)
            z = fmaf(hfull[k], sW1[j * H_DIM + k], z);
        z = tanh_fast(z);
        y0 = fmaf(z, sW2[j], y0);
        y1 = fmaf(z, sW2[H_DIM + j], y1);
    }
    reinterpret_cast<float2*>(out)[rowA + parity] = make_float2(y0, y1);
}

extern "C" void kernel_launch(void* const* d_in, const int* in_sizes, int n_in,
                              void* d_out, int out_size) {
    const float* x    = (const float*)d_in[0];
    const float* W_ih = (const float*)d_in[1];
    const float* W_hh = (const float*)d_in[2];
    const float* b_ih = (const float*)d_in[3];
    const float* b_hh = (const float*)d_in[4];
    const float* W1   = (const float*)d_in[5];
    const float* b1   = (const float*)d_in[6];
    const float* W2   = (const float*)d_in[7];
    const float* b2   = (const float*)d_in[8];
    float* out = (float*)d_out;

    lstm_split3_kernel<<<NCTA, NTHR>>>(x, W_ih, W_hh, b_ih, b_hh,
                                       W1, b1, W2, b2, out);
}

// round 14
// speedup vs baseline: 1.1036x; 1.1036x over previous
#include <cuda_runtime.h>
#include <cuda_bf16.h>

// LSTM_20452634263894: B=32768, T=512, I=2, H=16.
// R0 skeleton (1 thread per batch row — the only layout that never spills)
// with three register-footprint / latency fixes:
//  - bias kept in SMEM (frees the 64-reg biasr cache; +16 LDS.128/step)
//  - packed f32x2 activation (validated: identical rel_err in R10/R11/R12)
//  - i/f/o rows pre-scaled by 0.5 (sigmoid = 0.5*tanh(pre)+0.5)
//  - one-step float2 x prefetch (hides LDG latency; +2 regs)
// All local arrays constant-indexed; no pointer selection of locals.

#define B_TOT 32768
#define T_LEN 512
#define I_DIM 2
#define H_DIM 16
#define NP    32   // gate pairs: p=0..7 i, 8..15 f, 16..23 g, 24..31 o

typedef unsigned long long u64;

__device__ __forceinline__ u64 pack2(float lo, float hi) {
    u64 r;
    asm("mov.b64 %0, {%1, %2};" : "=l"(r) : "f"(lo), "f"(hi));
    return r;
}
__device__ __forceinline__ void unpack2(u64 v, float& lo, float& hi) {
    asm("mov.b64 {%0, %1}, %2;" : "=f"(lo), "=f"(hi) : "l"(v));
}
__device__ __forceinline__ u64 ffma2(u64 a, u64 b, u64 c) {
    u64 d;
    asm("fma.rn.f32x2 %0, %1, %2, %3;" : "=l"(d) : "l"(a), "l"(b), "l"(c));
    return d;
}
__device__ __forceinline__ u64 mul2(u64 a, u64 b) {
    u64 d;
    asm("mul.rn.f32x2 %0, %1, %2;" : "=l"(d) : "l"(a), "l"(b));
    return d;
}
__device__ __forceinline__ float tanh_fast(float x) {
    float y;
    asm("tanh.approx.f32 %0, %1;" : "=f"(y) : "f"(x));
    return y;
}

// Gate-pair p -> 0.5 prescale for i/f/o rows, 1.0 for g (p in [16,24)).
__device__ __forceinline__ float pscale(int p) {
    return (p >= 16 && p < 24) ? 1.0f : 0.5f;
}

__global__ void __launch_bounds__(128, 2) lstm_lean_kernel(
    const float* __restrict__ x,
    const float* __restrict__ W_ih, const float* __restrict__ W_hh,
    const float* __restrict__ b_ih, const float* __restrict__ b_hh,
    const float* __restrict__ W1,  const float* __restrict__ b1,
    const float* __restrict__ W2,  const float* __restrict__ b2,
    float* __restrict__ out)
{
    // sWhh[k][p] = (W_hh[2p][k], W_hh[2p+1][k]) * pscale(p)
    __shared__ __align__(16) u64 sWhh[H_DIM][NP];
    __shared__ __align__(16) u64 sWih[2][NP];
    __shared__ __align__(16) u64 sBias[NP];
    __shared__ float sW1[H_DIM * H_DIM];
    __shared__ float sb1[H_DIM];
    __shared__ float sW2[I_DIM * H_DIM];
    __shared__ float sb2[I_DIM];

    const int tid = threadIdx.x;

    for (int idx = tid; idx < H_DIM * NP; idx += blockDim.x) {
        int k = idx / NP, p = idx % NP;
        float sc = pscale(p);
        sWhh[k][p] = pack2(W_hh[(2 * p) * H_DIM + k] * sc,
                           W_hh[(2 * p + 1) * H_DIM + k] * sc);
    }
    for (int idx = tid; idx < 2 * NP; idx += blockDim.x) {
        int cc = idx / NP, p = idx % NP;
        float sc = pscale(p);
        sWih[cc][p] = pack2(W_ih[(2 * p) * I_DIM + cc] * sc,
                            W_ih[(2 * p + 1) * I_DIM + cc] * sc);
    }
    for (int p = tid; p < NP; p += blockDim.x) {
        float sc = pscale(p);
        sBias[p] = pack2((b_ih[2 * p] + b_hh[2 * p]) * sc,
                         (b_ih[2 * p + 1] + b_hh[2 * p + 1]) * sc);
    }
    for (int idx = tid; idx < H_DIM * H_DIM; idx += blockDim.x) sW1[idx] = W1[idx];
    for (int idx = tid; idx < H_DIM; idx += blockDim.x) sb1[idx] = b1[idx];
    for (int idx = tid; idx < I_DIM * H_DIM; idx += blockDim.x) sW2[idx] = W2[idx];
    for (int idx = tid; idx < I_DIM; idx += blockDim.x) sb2[idx] = b2[idx];
    __syncthreads();

    const int b = blockIdx.x * blockDim.x + tid;
    const float2* __restrict__ xrow =
        reinterpret_cast<const float2*>(x) + (size_t)b * T_LEN;

    float h[H_DIM];
    u64   c2[8];                  // c2[j] = (c[2j], c[2j+1])
#pragma unroll
    for (int u = 0; u < H_DIM; ++u) h[u] = 0.0f;
#pragma unroll
    for (int j = 0; j < 8; ++j) c2[j] = 0ull;

    const u64 H05 = pack2(0.5f, 0.5f);

    const ulonglong2* __restrict__ bp =
        reinterpret_cast<const ulonglong2*>(&sBias[0]);
    const ulonglong2* __restrict__ wih0 =
        reinterpret_cast<const ulonglong2*>(&sWih[0][0]);
    const ulonglong2* __restrict__ wih1 =
        reinterpret_cast<const ulonglong2*>(&sWih[1][0]);

    float2 xb = __ldg(xrow);      // step 0, prefetched

#pragma unroll 1
    for (int t = 0; t < T_LEN; ++t) {
        const int tn = (t + 1 < T_LEN) ? (t + 1) : t;   // clamped
        float2 xn = __ldg(xrow + tn);                   // next step, hidden

        const u64 px0 = pack2(xb.x, xb.x);
        const u64 px1 = pack2(xb.y, xb.y);

        u64 acc[NP];
        // acc = bias(smem) + x0*Wih[:,0] + x1*Wih[:,1]
#pragma unroll
        for (int p2 = 0; p2 < NP / 2; ++p2) {
            ulonglong2 bb = bp[p2];
            ulonglong2 w0 = wih0[p2];
            ulonglong2 w1 = wih1[p2];
            acc[2 * p2]     = ffma2(px1, w1.x, ffma2(px0, w0.x, bb.x));
            acc[2 * p2 + 1] = ffma2(px1, w1.y, ffma2(px0, w0.y, bb.y));
        }
        // Recurrent matvec: acc[p] += h[k] * Whh_pair[k][p]
#pragma unroll
        for (int k = 0; k < H_DIM; ++k) {
            const u64 hk = pack2(h[k], h[k]);
            const ulonglong2* __restrict__ row =
                reinterpret_cast<const ulonglong2*>(&sWhh[k][0]);
#pragma unroll
            for (int p2 = 0; p2 < NP / 2; ++p2) {
                ulonglong2 w = row[p2];
                acc[2 * p2]     = ffma2(hk, w.x, acc[2 * p2]);
                acc[2 * p2 + 1] = ffma2(hk, w.y, acc[2 * p2 + 1]);
            }
        }
        // Packed activation (validated layout): acc[j]=i, acc[8+j]=f,
        // acc[16+j]=g, acc[24+j]=o for unit pair (2j,2j+1); i/f/o have the
        // 0.5 folded into weights+bias.
#pragma unroll
        for (int j = 0; j < 8; ++j) {
            float u, v;
            unpack2(acc[j], u, v);
            u64 i2 = ffma2(H05, pack2(tanh_fast(u), tanh_fast(v)), H05);
            unpack2(acc[8 + j], u, v);
            u64 f2 = ffma2(H05, pack2(tanh_fast(u), tanh_fast(v)), H05);
            unpack2(acc[16 + j], u, v);
            u64 g2 = pack2(tanh_fast(u), tanh_fast(v));
            unpack2(acc[24 + j], u, v);
            u64 o2 = ffma2(H05, pack2(tanh_fast(u), tanh_fast(v)), H05);
            u64 cn = ffma2(f2, c2[j], mul2(i2, g2));
            c2[j] = cn;
            unpack2(cn, u, v);
            u64 hv = mul2(o2, pack2(tanh_fast(u), tanh_fast(v)));
            unpack2(hv, h[2 * j], h[2 * j + 1]);    // constant indices
        }

        xb = xn;
    }

    // MLP head: y = tanh(h @ W1^T + b1) @ W2^T + b2
    float y0 = sb2[0], y1 = sb2[1];
#pragma unroll
    for (int j = 0; j < H_DIM; ++j) {
        float z = sb1[j];
#pragma unroll
        for (int k = 0; k < H_DIM; ++k) z = fmaf(h[k], sW1[j * H_DIM + k], z);
        z = tanh_fast(z);
        y0 = fmaf(z, sW2[0 * H_DIM + j], y0);
        y1 = fmaf(z, sW2[1 * H_DIM + j], y1);
    }
    reinterpret_cast<float2*>(out)[b] = make_float2(y0, y1);
}

extern "C" void kernel_launch(void* const* d_in, const int* in_sizes, int n_in,
                              void* d_out, int out_size) {
    const float* x    = (const float*)d_in[0];
    const float* W_ih = (const float*)d_in[1];
    const float* W_hh = (const float*)d_in[2];
    const float* b_ih = (const float*)d_in[3];
    const float* b_hh = (const float*)d_in[4];
    const float* W1   = (const float*)d_in[5];
    const float* b1   = (const float*)d_in[6];
    const float* W2   = (const float*)d_in[7];
    const float* b2   = (const float*)d_in[8];
    float* out = (float*)d_out;

    dim3 block(128);
    dim3 grid(B_TOT / 128);   // 256 CTAs, one thread per batch row
    lstm_lean_kernel<<<grid, block>>>(x, W_ih, W_hh, b_ih, b_hh,
                                      W1, b1, W2, b2, out);
}

// round 15
// speedup vs baseline: 2.0783x; 1.8831x over previous
#include <cuda_runtime.h>
#include <cuda_bf16.h>

// LSTM_20452634263894: B=32768, T=512, I=2, H=16.
// NEW decomposition: one WARP handles 2 batch rows; lane l -> row half
// (l>>4) and hidden unit u = l&15. Each lane holds the 4 gate rows of
// W_hh/W_ih for its unit IN REGISTERS (packed (i,f) and (g,o) u64 pairs,
// i/f/o pre-scaled by 0.5). NO shared-memory traffic in the timestep loop;
// h broadcast via 16 shfl.idx per step. sigmoid = 0.5*tanh(pre)+0.5.

#define B_TOT 32768
#define T_LEN 512
#define H_DIM 16
#define NTHR  128            // 4 warps/CTA -> 8 rows/CTA
#define NCTA  (B_TOT / 8)    // 4096 CTAs

typedef unsigned long long u64;

__device__ __forceinline__ u64 pack2(float lo, float hi) {
    u64 r;
    asm("mov.b64 %0, {%1, %2};" : "=l"(r) : "f"(lo), "f"(hi));
    return r;
}
__device__ __forceinline__ void unpack2(u64 v, float& lo, float& hi) {
    asm("mov.b64 {%0, %1}, %2;" : "=f"(lo), "=f"(hi) : "l"(v));
}
__device__ __forceinline__ u64 ffma2(u64 a, u64 b, u64 c) {
    u64 d;
    asm("fma.rn.f32x2 %0, %1, %2, %3;" : "=l"(d) : "l"(a), "l"(b), "l"(c));
    return d;
}
__device__ __forceinline__ float tanh_fast(float x) {
    float y;
    asm("tanh.approx.f32 %0, %1;" : "=f"(y) : "f"(x));
    return y;
}

__global__ void __launch_bounds__(NTHR) lstm_warp_kernel(
    const float* __restrict__ x,
    const float* __restrict__ W_ih, const float* __restrict__ W_hh,
    const float* __restrict__ b_ih, const float* __restrict__ b_hh,
    const float* __restrict__ W1,  const float* __restrict__ b1,
    const float* __restrict__ W2,  const float* __restrict__ b2,
    float* __restrict__ out)
{
    // Shared memory only for the one-time MLP head.
    __shared__ float sW1[H_DIM * H_DIM];
    __shared__ float sb1[H_DIM];
    __shared__ float sW2[2 * H_DIM];
    __shared__ float sb2[2];

    const int tid = threadIdx.x;
    for (int i = tid; i < H_DIM * H_DIM; i += NTHR) sW1[i] = W1[i];
    for (int i = tid; i < H_DIM; i += NTHR) sb1[i] = b1[i];
    for (int i = tid; i < 2 * H_DIM; i += NTHR) sW2[i] = W2[i];
    for (int i = tid; i < 2; i += NTHR) sb2[i] = b2[i];
    __syncthreads();

    const int lane = tid & 31;
    const int wCta = tid >> 5;                       // warp in CTA (0..3)
    const int hsel = lane & 16;                      // 0 or 16 (row half tag)
    const int u    = lane & 15;                      // owned hidden unit
    const int row  = (blockIdx.x * 4 + wCta) * 2 + (lane >> 4);

    // One-time weight load + pack. Gate rows (torch order): i=u, f=16+u,
    // g=32+u, o=48+u. i/f/o pre-scaled by 0.5.
    u64 w_if[H_DIM], w_go[H_DIM];
#pragma unroll
    for (int k = 0; k < H_DIM; ++k) {
        w_if[k] = pack2(W_hh[u * H_DIM + k] * 0.5f,
                        W_hh[(16 + u) * H_DIM + k] * 0.5f);
        w_go[k] = pack2(W_hh[(32 + u) * H_DIM + k],
                        W_hh[(48 + u) * H_DIM + k] * 0.5f);
    }
    const u64 wif0 = pack2(W_ih[u * 2 + 0] * 0.5f, W_ih[(16 + u) * 2 + 0] * 0.5f);
    const u64 wif1 = pack2(W_ih[u * 2 + 1] * 0.5f, W_ih[(16 + u) * 2 + 1] * 0.5f);
    const u64 wgo0 = pack2(W_ih[(32 + u) * 2 + 0],  W_ih[(48 + u) * 2 + 0] * 0.5f);
    const u64 wgo1 = pack2(W_ih[(32 + u) * 2 + 1],  W_ih[(48 + u) * 2 + 1] * 0.5f);
    const u64 b_if = pack2((b_ih[u] + b_hh[u]) * 0.5f,
                           (b_ih[16 + u] + b_hh[16 + u]) * 0.5f);
    const u64 b_go = pack2(b_ih[32 + u] + b_hh[32 + u],
                           (b_ih[48 + u] + b_hh[48 + u]) * 0.5f);

    const float2* __restrict__ xrow =
        reinterpret_cast<const float2*>(x) + (size_t)row * T_LEN;

    float h = 0.0f, c = 0.0f;
    float2 xb = __ldg(xrow);                          // step 0, prefetched

#pragma unroll 1
    for (int t = 0; t < T_LEN; ++t) {
        const int tn = (t + 1 < T_LEN) ? (t + 1) : t; // clamped
        float2 xn = __ldg(xrow + tn);                 // next step, hidden

        const u64 px0 = pack2(xb.x, xb.x);
        const u64 px1 = pack2(xb.y, xb.y);
        u64 aif = ffma2(px1, wif1, ffma2(px0, wif0, b_if));
        u64 ago = ffma2(px1, wgo1, ffma2(px0, wgo0, b_go));

        // Recurrent matvec: broadcast h[k] of MY row half via shfl.idx.
#pragma unroll
        for (int k = 0; k < H_DIM; ++k) {
            const float hk = __shfl_sync(0xffffffffu, h, k | hsel);
            const u64 hk2 = pack2(hk, hk);
            aif = ffma2(hk2, w_if[k], aif);
            ago = ffma2(hk2, w_go[k], ago);
        }

        float ipre, fpre, gpre, opre;
        unpack2(aif, ipre, fpre);
        unpack2(ago, gpre, opre);
        const float iv = fmaf(0.5f, tanh_fast(ipre), 0.5f);
        const float fv = fmaf(0.5f, tanh_fast(fpre), 0.5f);
        const float gv = tanh_fast(gpre);
        const float ov = fmaf(0.5f, tanh_fast(opre), 0.5f);
        c = fmaf(fv, c, iv * gv);
        h = ov * tanh_fast(c);

        xb = xn;
    }

    // MLP head: z_u = tanh(b1[u] + sum_k h_k*W1[u][k]); y = z @ W2^T + b2.
    float z = sb1[u];
#pragma unroll
    for (int k = 0; k < H_DIM; ++k) {
        const float hk = __shfl_sync(0xffffffffu, h, k | hsel);
        z = fmaf(hk, sW1[u * H_DIM + k], z);
    }
    z = tanh_fast(z);
    float p0 = z * sW2[u];            // W2[0][u]
    float p1 = z * sW2[H_DIM + u];    // W2[1][u]
    // Butterfly reduction within the 16-lane half (xor<16 stays in-half).
#pragma unroll
    for (int off = 1; off < H_DIM; off <<= 1) {
        p0 += __shfl_xor_sync(0xffffffffu, p0, off);
        p1 += __shfl_xor_sync(0xffffffffu, p1, off);
    }
    if (u == 0) {
        reinterpret_cast<float2*>(out)[row] =
            make_float2(p0 + sb2[0], p1 + sb2[1]);
    }
}

extern "C" void kernel_launch(void* const* d_in, const int* in_sizes, int n_in,
                              void* d_out, int out_size) {
    const float* x    = (const float*)d_in[0];
    const float* W_ih = (const float*)d_in[1];
    const float* W_hh = (const float*)d_in[2];
    const float* b_ih = (const float*)d_in[3];
    const float* b_hh = (const float*)d_in[4];
    const float* W1   = (const float*)d_in[5];
    const float* b1   = (const float*)d_in[6];
    const float* W2   = (const float*)d_in[7];
    const float* b2   = (const float*)d_in[8];
    float* out = (float*)d_out;

    lstm_warp_kernel<<<NCTA, NTHR>>>(x, W_ih, W_hh, b_ih, b_hh,
                                     W1, b1, W2, b2, out);
}

// round 16
// speedup vs baseline: 2.4256x; 1.1671x over previous
#include <cuda_runtime.h>
#include <cuda_bf16.h>

// LSTM_20452634263894: B=32768, T=512, I=2, H=16.
// Row-packed f32x2 decomposition: lane u (=lane&15) owns hidden unit u for
// TWO batch rows packed in each u64: h=(h_A[u],h_B[u]), c likewise. Warp
// covers 4 rows (lane halves -> row pairs). Weights live in REGISTERS,
// duplicated (w,w) once at init, so the matvec needs NO per-step dup packs:
// one u64 shfl delivers (h_A[k],h_B[k]) ready for ffma2. No smem in loop.
// i/f/o rows pre-scaled by 0.5 (sigmoid = 0.5*tanh(pre)+0.5).

#define B_TOT 32768
#define T_LEN 512
#define H_DIM 16
#define NTHR  128            // 4 warps/CTA -> 16 rows/CTA
#define NCTA  (B_TOT / 16)   // 2048 CTAs

typedef unsigned long long u64;

__device__ __forceinline__ u64 pack2(float lo, float hi) {
    u64 r;
    asm("mov.b64 %0, {%1, %2};" : "=l"(r) : "f"(lo), "f"(hi));
    return r;
}
__device__ __forceinline__ void unpack2(u64 v, float& lo, float& hi) {
    asm("mov.b64 {%0, %1}, %2;" : "=f"(lo), "=f"(hi) : "l"(v));
}
__device__ __forceinline__ u64 ffma2(u64 a, u64 b, u64 c) {
    u64 d;
    asm("fma.rn.f32x2 %0, %1, %2, %3;" : "=l"(d) : "l"(a), "l"(b), "l"(c));
    return d;
}
__device__ __forceinline__ u64 mul2(u64 a, u64 b) {
    u64 d;
    asm("mul.rn.f32x2 %0, %1, %2;" : "=l"(d) : "l"(a), "l"(b));
    return d;
}
__device__ __forceinline__ u64 add2(u64 a, u64 b) {
    u64 d;
    asm("add.rn.f32x2 %0, %1, %2;" : "=l"(d) : "l"(a), "l"(b));
    return d;
}
__device__ __forceinline__ float tanh_fast(float x) {
    float y;
    asm("tanh.approx.f32 %0, %1;" : "=f"(y) : "f"(x));
    return y;
}
__device__ __forceinline__ u64 dup(float w) { return pack2(w, w); }

__global__ void __launch_bounds__(NTHR) lstm_rowpack_kernel(
    const float* __restrict__ x,
    const float* __restrict__ W_ih, const float* __restrict__ W_hh,
    const float* __restrict__ b_ih, const float* __restrict__ b_hh,
    const float* __restrict__ W1,  const float* __restrict__ b1,
    const float* __restrict__ W2,  const float* __restrict__ b2,
    float* __restrict__ out)
{
    // Shared memory only for the one-time MLP head.
    __shared__ float sW1[H_DIM * H_DIM];
    __shared__ float sb1[H_DIM];
    __shared__ float sW2[2 * H_DIM];
    __shared__ float sb2[2];

    const int tid = threadIdx.x;
    for (int i = tid; i < H_DIM * H_DIM; i += NTHR) sW1[i] = W1[i];
    for (int i = tid; i < H_DIM; i += NTHR) sb1[i] = b1[i];
    for (int i = tid; i < 2 * H_DIM; i += NTHR) sW2[i] = W2[i];
    for (int i = tid; i < 2; i += NTHR) sb2[i] = b2[i];
    __syncthreads();

    const int lane = tid & 31;
    const int wCta = tid >> 5;               // warp in CTA (0..3)
    const int u    = lane & 15;              // owned hidden unit
    const int hsel = lane & 16;              // row-pair selector
    // Warp covers 4 rows; this lane's pair:
    const int rowA = (blockIdx.x * 4 + wCta) * 4 + ((lane >> 4) << 1);
    const int rowB = rowA + 1;

    // One-time weight load, duplicated (w,w) for row-packed ffma2.
    // Gate rows (torch order): i=u, f=16+u, g=32+u, o=48+u. i/f/o scaled 0.5.
    u64 wI[H_DIM], wF[H_DIM], wG[H_DIM], wO[H_DIM];
#pragma unroll
    for (int k = 0; k < H_DIM; ++k) {
        wI[k] = dup(W_hh[u * H_DIM + k] * 0.5f);
        wF[k] = dup(W_hh[(16 + u) * H_DIM + k] * 0.5f);
        wG[k] = dup(W_hh[(32 + u) * H_DIM + k]);
        wO[k] = dup(W_hh[(48 + u) * H_DIM + k] * 0.5f);
    }
    const u64 uI0 = dup(W_ih[u * 2 + 0] * 0.5f),        uI1 = dup(W_ih[u * 2 + 1] * 0.5f);
    const u64 uF0 = dup(W_ih[(16 + u) * 2 + 0] * 0.5f), uF1 = dup(W_ih[(16 + u) * 2 + 1] * 0.5f);
    const u64 uG0 = dup(W_ih[(32 + u) * 2 + 0]),        uG1 = dup(W_ih[(32 + u) * 2 + 1]);
    const u64 uO0 = dup(W_ih[(48 + u) * 2 + 0] * 0.5f), uO1 = dup(W_ih[(48 + u) * 2 + 1] * 0.5f);
    const u64 bI = dup((b_ih[u] + b_hh[u]) * 0.5f);
    const u64 bF = dup((b_ih[16 + u] + b_hh[16 + u]) * 0.5f);
    const u64 bG = dup(b_ih[32 + u] + b_hh[32 + u]);
    const u64 bO = dup((b_ih[48 + u] + b_hh[48 + u]) * 0.5f);

    const float2* __restrict__ xpA =
        reinterpret_cast<const float2*>(x) + (size_t)rowA * T_LEN;
    const float2* __restrict__ xpB =
        reinterpret_cast<const float2*>(x) + (size_t)rowB * T_LEN;

    u64 h = 0ull, c = 0ull;                  // (rowA, rowB) packed
    const u64 H05 = pack2(0.5f, 0.5f);

    float2 xbA = __ldg(xpA);
    float2 xbB = __ldg(xpB);

#pragma unroll 1
    for (int t = 0; t < T_LEN; ++t) {
        const int tn = (t + 1 < T_LEN) ? (t + 1) : t;   // clamped
        float2 xnA = __ldg(xpA + tn);
        float2 xnB = __ldg(xpB + tn);

        const u64 px0 = pack2(xbA.x, xbB.x);
        const u64 px1 = pack2(xbA.y, xbB.y);
        u64 aI = ffma2(px1, uI1, ffma2(px0, uI0, bI));
        u64 aF = ffma2(px1, uF1, ffma2(px0, uF0, bF));
        u64 aG = ffma2(px1, uG1, ffma2(px0, uG0, bG));
        u64 aO = ffma2(px1, uO1, ffma2(px0, uO0, bO));

        // Recurrent matvec: one u64 shfl delivers (h_A[k], h_B[k]).
#pragma unroll
        for (int k = 0; k < H_DIM; ++k) {
            const u64 hk = __shfl_sync(0xffffffffu, h, k | hsel);
            aI = ffma2(hk, wI[k], aI);
            aF = ffma2(hk, wF[k], aF);
            aG = ffma2(hk, wG[k], aG);
            aO = ffma2(hk, wO[k], aO);
        }

        // Activation (both rows packed; tanh is scalar).
        float lo, hi;
        unpack2(aI, lo, hi);
        const u64 i2 = ffma2(H05, pack2(tanh_fast(lo), tanh_fast(hi)), H05);
        unpack2(aF, lo, hi);
        const u64 f2 = ffma2(H05, pack2(tanh_fast(lo), tanh_fast(hi)), H05);
        unpack2(aG, lo, hi);
        const u64 g2 = pack2(tanh_fast(lo), tanh_fast(hi));
        unpack2(aO, lo, hi);
        const u64 o2 = ffma2(H05, pack2(tanh_fast(lo), tanh_fast(hi)), H05);
        c = ffma2(f2, c, mul2(i2, g2));
        unpack2(c, lo, hi);
        h = mul2(o2, pack2(tanh_fast(lo), tanh_fast(hi)));

        xbA = xnA; xbB = xnB;
    }

    // MLP head, row-packed: z_u = tanh(b1[u] + sum_k h_k*W1[u][k]).
    u64 z = dup(sb1[u]);
#pragma unroll
    for (int k = 0; k < H_DIM; ++k) {
        const u64 hk = __shfl_sync(0xffffffffu, h, k | hsel);
        z = ffma2(hk, dup(sW1[u * H_DIM + k]), z);
    }
    float zlo, zhi;
    unpack2(z, zlo, zhi);
    const u64 t2 = pack2(tanh_fast(zlo), tanh_fast(zhi));
    u64 p0 = mul2(t2, dup(sW2[u]));            // W2[0][u]
    u64 p1 = mul2(t2, dup(sW2[H_DIM + u]));    // W2[1][u]
    // Butterfly reduction over the 16-lane half (xor<16 stays in-half).
#pragma unroll
    for (int off = 1; off < H_DIM; off <<= 1) {
        p0 = add2(p0, __shfl_xor_sync(0xffffffffu, p0, off));
        p1 = add2(p1, __shfl_xor_sync(0xffffffffu, p1, off));
    }
    if (u == 0) {
        float y0A, y0B, y1A, y1B;
        unpack2(p0, y0A, y0B);
        unpack2(p1, y1A, y1B);
        reinterpret_cast<float2*>(out)[rowA] =
            make_float2(y0A + sb2[0], y1A + sb2[1]);
        reinterpret_cast<float2*>(out)[rowB] =
            make_float2(y0B + sb2[0], y1B + sb2[1]);
    }
}

extern "C" void kernel_launch(void* const* d_in, const int* in_sizes, int n_in,
                              void* d_out, int out_size) {
    const float* x    = (const float*)d_in[0];
    const float* W_ih = (const float*)d_in[1];
    const float* W_hh = (const float*)d_in[2];
    const float* b_ih = (const float*)d_in[3];
    const float* b_hh = (const float*)d_in[4];
    const float* W1   = (const float*)d_in[5];
    const float* b1   = (const float*)d_in[6];
    const float* W2   = (const float*)d_in[7];
    const float* b2   = (const float*)d_in[8];
    float* out = (float*)d_out;

    lstm_rowpack_kernel<<<NCTA, NTHR>>>(x, W_ih, W_hh, b_ih, b_hh,
                                        W1, b1, W2, b2, out);
}

// round 17
// speedup vs baseline: 2.5885x; 1.0672x over previous
#include <cuda_runtime.h>
#include <cuda_bf16.h>

// LSTM_20452634263894: B=32768, T=512, I=2, H=16.
// R15 row-packed decomposition x2: lane u (=lane&15) owns hidden unit u for
// TWO independent packed row-pairs: h0=(q,q+1), h1=(q+2,q+3). Warp covers
// 8 rows. Weights in registers, duplicated (w,w) once at init, REUSED by
// both row-pairs (no extra weight regs). One u64 shfl per (k, pair) gives
// (hA[k],hB[k]) ready for ffma2. 8 independent FMA chains per k for ILP.
// i/f/o rows pre-scaled by 0.5 (sigmoid = 0.5*tanh(pre)+0.5).

#define B_TOT 32768
#define T_LEN 512
#define H_DIM 16
#define NTHR  128            // 4 warps/CTA -> 32 rows/CTA
#define NCTA  (B_TOT / 32)   // 1024 CTAs

typedef unsigned long long u64;

__device__ __forceinline__ u64 pack2(float lo, float hi) {
    u64 r;
    asm("mov.b64 %0, {%1, %2};" : "=l"(r) : "f"(lo), "f"(hi));
    return r;
}
__device__ __forceinline__ void unpack2(u64 v, float& lo, float& hi) {
    asm("mov.b64 {%0, %1}, %2;" : "=f"(lo), "=f"(hi) : "l"(v));
}
__device__ __forceinline__ u64 ffma2(u64 a, u64 b, u64 c) {
    u64 d;
    asm("fma.rn.f32x2 %0, %1, %2, %3;" : "=l"(d) : "l"(a), "l"(b), "l"(c));
    return d;
}
__device__ __forceinline__ u64 mul2(u64 a, u64 b) {
    u64 d;
    asm("mul.rn.f32x2 %0, %1, %2;" : "=l"(d) : "l"(a), "l"(b));
    return d;
}
__device__ __forceinline__ u64 add2(u64 a, u64 b) {
    u64 d;
    asm("add.rn.f32x2 %0, %1, %2;" : "=l"(d) : "l"(a), "l"(b));
    return d;
}
__device__ __forceinline__ float tanh_fast(float x) {
    float y;
    asm("tanh.approx.f32 %0, %1;" : "=f"(y) : "f"(x));
    return y;
}
__device__ __forceinline__ u64 dup(float w) { return pack2(w, w); }

__global__ void __launch_bounds__(NTHR) lstm_rowpack2_kernel(
    const float* __restrict__ x,
    const float* __restrict__ W_ih, const float* __restrict__ W_hh,
    const float* __restrict__ b_ih, const float* __restrict__ b_hh,
    const float* __restrict__ W1,  const float* __restrict__ b1,
    const float* __restrict__ W2,  const float* __restrict__ b2,
    float* __restrict__ out)
{
    // Shared memory only for the one-time MLP head.
    __shared__ float sW1[H_DIM * H_DIM];
    __shared__ float sb1[H_DIM];
    __shared__ float sW2[2 * H_DIM];
    __shared__ float sb2[2];

    const int tid = threadIdx.x;
    for (int i = tid; i < H_DIM * H_DIM; i += NTHR) sW1[i] = W1[i];
    for (int i = tid; i < H_DIM; i += NTHR) sb1[i] = b1[i];
    for (int i = tid; i < 2 * H_DIM; i += NTHR) sW2[i] = W2[i];
    for (int i = tid; i < 2; i += NTHR) sb2[i] = b2[i];
    __syncthreads();

    const int lane = tid & 31;
    const int wCta = tid >> 5;               // warp in CTA (0..3)
    const int u    = lane & 15;              // owned hidden unit
    const int hsel = lane & 16;              // lane-half selector
    // Warp covers 8 rows; this lane-half's quad starts at:
    const int q = (blockIdx.x * 4 + wCta) * 8 + ((lane >> 4) << 2);

    // One-time weight load, duplicated (w,w). Gate rows (torch order):
    // i=u, f=16+u, g=32+u, o=48+u. i/f/o pre-scaled by 0.5.
    u64 wI[H_DIM], wF[H_DIM], wG[H_DIM], wO[H_DIM];
#pragma unroll
    for (int k = 0; k < H_DIM; ++k) {
        wI[k] = dup(W_hh[u * H_DIM + k] * 0.5f);
        wF[k] = dup(W_hh[(16 + u) * H_DIM + k] * 0.5f);
        wG[k] = dup(W_hh[(32 + u) * H_DIM + k]);
        wO[k] = dup(W_hh[(48 + u) * H_DIM + k] * 0.5f);
    }
    const u64 uI0 = dup(W_ih[u * 2 + 0] * 0.5f),        uI1 = dup(W_ih[u * 2 + 1] * 0.5f);
    const u64 uF0 = dup(W_ih[(16 + u) * 2 + 0] * 0.5f), uF1 = dup(W_ih[(16 + u) * 2 + 1] * 0.5f);
    const u64 uG0 = dup(W_ih[(32 + u) * 2 + 0]),        uG1 = dup(W_ih[(32 + u) * 2 + 1]);
    const u64 uO0 = dup(W_ih[(48 + u) * 2 + 0] * 0.5f), uO1 = dup(W_ih[(48 + u) * 2 + 1] * 0.5f);
    const u64 bI = dup((b_ih[u] + b_hh[u]) * 0.5f);
    const u64 bF = dup((b_ih[16 + u] + b_hh[16 + u]) * 0.5f);
    const u64 bG = dup(b_ih[32 + u] + b_hh[32 + u]);
    const u64 bO = dup((b_ih[48 + u] + b_hh[48 + u]) * 0.5f);

    const float2* __restrict__ xp0A = reinterpret_cast<const float2*>(x) + (size_t)(q + 0) * T_LEN;
    const float2* __restrict__ xp0B = reinterpret_cast<const float2*>(x) + (size_t)(q + 1) * T_LEN;
    const float2* __restrict__ xp1A = reinterpret_cast<const float2*>(x) + (size_t)(q + 2) * T_LEN;
    const float2* __restrict__ xp1B = reinterpret_cast<const float2*>(x) + (size_t)(q + 3) * T_LEN;

    u64 h0 = 0ull, c0 = 0ull;                // rows (q, q+1) packed
    u64 h1 = 0ull, c1 = 0ull;                // rows (q+2, q+3) packed
    const u64 H05 = pack2(0.5f, 0.5f);

    float2 xb0A = __ldg(xp0A), xb0B = __ldg(xp0B);
    float2 xb1A = __ldg(xp1A), xb1B = __ldg(xp1B);

#pragma unroll 1
    for (int t = 0; t < T_LEN; ++t) {
        const int tn = (t + 1 < T_LEN) ? (t + 1) : t;   // clamped
        float2 xn0A = __ldg(xp0A + tn), xn0B = __ldg(xp0B + tn);
        float2 xn1A = __ldg(xp1A + tn), xn1B = __ldg(xp1B + tn);

        const u64 p00 = pack2(xb0A.x, xb0B.x);
        const u64 p01 = pack2(xb0A.y, xb0B.y);
        const u64 p10 = pack2(xb1A.x, xb1B.x);
        const u64 p11 = pack2(xb1A.y, xb1B.y);
        u64 aI0 = ffma2(p01, uI1, ffma2(p00, uI0, bI));
        u64 aF0 = ffma2(p01, uF1, ffma2(p00, uF0, bF));
        u64 aG0 = ffma2(p01, uG1, ffma2(p00, uG0, bG));
        u64 aO0 = ffma2(p01, uO1, ffma2(p00, uO0, bO));
        u64 aI1 = ffma2(p11, uI1, ffma2(p10, uI0, bI));
        u64 aF1 = ffma2(p11, uF1, ffma2(p10, uF0, bF));
        u64 aG1 = ffma2(p11, uG1, ffma2(p10, uG0, bG));
        u64 aO1 = ffma2(p11, uO1, ffma2(p10, uO0, bO));

        // Recurrent matvec: 2 u64 shfls + 8 independent ffma2 chains per k.
#pragma unroll
        for (int k = 0; k < H_DIM; ++k) {
            const u64 hk0 = __shfl_sync(0xffffffffu, h0, k | hsel);
            const u64 hk1 = __shfl_sync(0xffffffffu, h1, k | hsel);
            aI0 = ffma2(hk0, wI[k], aI0);
            aF0 = ffma2(hk0, wF[k], aF0);
            aG0 = ffma2(hk0, wG[k], aG0);
            aO0 = ffma2(hk0, wO[k], aO0);
            aI1 = ffma2(hk1, wI[k], aI1);
            aF1 = ffma2(hk1, wF[k], aF1);
            aG1 = ffma2(hk1, wG[k], aG1);
            aO1 = ffma2(hk1, wO[k], aO1);
        }

        // Activation, set 0 (rows q, q+1).
        {
            float lo, hi;
            unpack2(aI0, lo, hi);
            const u64 i2 = ffma2(H05, pack2(tanh_fast(lo), tanh_fast(hi)), H05);
            unpack2(aF0, lo, hi);
            const u64 f2 = ffma2(H05, pack2(tanh_fast(lo), tanh_fast(hi)), H05);
            unpack2(aG0, lo, hi);
            const u64 g2 = pack2(tanh_fast(lo), tanh_fast(hi));
            unpack2(aO0, lo, hi);
            const u64 o2 = ffma2(H05, pack2(tanh_fast(lo), tanh_fast(hi)), H05);
            c0 = ffma2(f2, c0, mul2(i2, g2));
            unpack2(c0, lo, hi);
            h0 = mul2(o2, pack2(tanh_fast(lo), tanh_fast(hi)));
        }
        // Activation, set 1 (rows q+2, q+3).
        {
            float lo, hi;
            unpack2(aI1, lo, hi);
            const u64 i2 = ffma2(H05, pack2(tanh_fast(lo), tanh_fast(hi)), H05);
            unpack2(aF1, lo, hi);
            const u64 f2 = ffma2(H05, pack2(tanh_fast(lo), tanh_fast(hi)), H05);
            unpack2(aG1, lo, hi);
            const u64 g2 = pack2(tanh_fast(lo), tanh_fast(hi));
            unpack2(aO1, lo, hi);
            const u64 o2 = ffma2(H05, pack2(tanh_fast(lo), tanh_fast(hi)), H05);
            c1 = ffma2(f2, c1, mul2(i2, g2));
            unpack2(c1, lo, hi);
            h1 = mul2(o2, pack2(tanh_fast(lo), tanh_fast(hi)));
        }

        xb0A = xn0A; xb0B = xn0B; xb1A = xn1A; xb1B = xn1B;
    }

    // MLP head for both packed pairs: z_u = tanh(b1[u] + sum_k h_k W1[u][k]).
    u64 z0 = dup(sb1[u]), z1 = dup(sb1[u]);
#pragma unroll
    for (int k = 0; k < H_DIM; ++k) {
        const u64 w1k = dup(sW1[u * H_DIM + k]);
        z0 = ffma2(__shfl_sync(0xffffffffu, h0, k | hsel), w1k, z0);
        z1 = ffma2(__shfl_sync(0xffffffffu, h1, k | hsel), w1k, z1);
    }
    float lo, hi;
    unpack2(z0, lo, hi);
    const u64 t20 = pack2(tanh_fast(lo), tanh_fast(hi));
    unpack2(z1, lo, hi);
    const u64 t21 = pack2(tanh_fast(lo), tanh_fast(hi));
    const u64 w2a = dup(sW2[u]);            // W2[0][u]
    const u64 w2b = dup(sW2[H_DIM + u]);    // W2[1][u]
    u64 p0_0 = mul2(t20, w2a), p1_0 = mul2(t20, w2b);
    u64 p0_1 = mul2(t21, w2a), p1_1 = mul2(t21, w2b);
    // Butterfly reduction over the 16-lane half (xor<16 stays in-half).
#pragma unroll
    for (int off = 1; off < H_DIM; off <<= 1) {
        p0_0 = add2(p0_0, __shfl_xor_sync(0xffffffffu, p0_0, off));
        p1_0 = add2(p1_0, __shfl_xor_sync(0xffffffffu, p1_0, off));
        p0_1 = add2(p0_1, __shfl_xor_sync(0xffffffffu, p0_1, off));
        p1_1 = add2(p1_1, __shfl_xor_sync(0xffffffffu, p1_1, off));
    }
    if (u == 0) {
        float y0A, y0B, y1A, y1B;
        unpack2(p0_0, y0A, y0B);
        unpack2(p1_0, y1A, y1B);
        reinterpret_cast<float2*>(out)[q + 0] = make_float2(y0A + sb2[0], y1A + sb2[1]);
        reinterpret_cast<float2*>(out)[q + 1] = make_float2(y0B + sb2[0], y1B + sb2[1]);
        unpack2(p0_1, y0A, y0B);
        unpack2(p1_1, y1A, y1B);
        reinterpret_cast<float2*>(out)[q + 2] = make_float2(y0A + sb2[0], y1A + sb2[1]);
        reinterpret_cast<float2*>(out)[q + 3] = make_float2(y0B + sb2[0], y1B + sb2[1]);
    }
}

extern "C" void kernel_launch(void* const* d_in, const int* in_sizes, int n_in,
                              void* d_out, int out_size) {
    const float* x    = (const float*)d_in[0];
    const float* W_ih = (const float*)d_in[1];
    const float* W_hh = (const float*)d_in[2];
    const float* b_ih = (const float*)d_in[3];
    const float* b_hh = (const float*)d_in[4];
    const float* W1   = (const float*)d_in[5];
    const float* b1   = (const float*)d_in[6];
    const float* W2   = (const float*)d_in[7];
    const float* b2   = (const float*)d_in[8];
    float* out = (float*)d_out;

    lstm_rowpack2_kernel<<<NCTA, NTHR>>>(x, W_ih, W_hh, b_ih, b_hh,
                                         W1, b1, W2, b2, out);
}